// round 15
// baseline (speedup 1.0000x reference)
#include <cuda_runtime.h>
#include <cuda_fp16.h>
#include <cstdint>
#include <math.h>

// Problem constants
#define NT 8192          // tokens = 4*2048
#define NH 1024          // hidden
#define NE 8             // experts
#define NI 4096          // intermediate
#define NPAIRS (2*NT)    // top-2 pairs

// ==================== PTX helpers ====================
__device__ __forceinline__ void mma16816(float* d, const uint32_t* a, const uint32_t* b) {
    asm volatile("mma.sync.aligned.m16n8k16.row.col.f32.f16.f16.f32 "
        "{%0,%1,%2,%3}, {%4,%5,%6,%7}, {%8,%9}, {%0,%1,%2,%3};"
        : "+f"(d[0]), "+f"(d[1]), "+f"(d[2]), "+f"(d[3])
        : "r"(a[0]), "r"(a[1]), "r"(a[2]), "r"(a[3]), "r"(b[0]), "r"(b[1]));
}
__device__ __forceinline__ uint32_t smem_u32(const void* p) {
    uint32_t a;
    asm("{ .reg .u64 t; cvta.to.shared.u64 t, %1; cvt.u32.u64 %0, t; }" : "=r"(a) : "l"(p));
    return a;
}
#define CP16(sm_addr, gptr) \
    asm volatile("cp.async.ca.shared.global [%0], [%1], 16;" \
                 :: "r"(sm_addr), "l"(gptr) : "memory")
#define CP_COMMIT() asm volatile("cp.async.commit_group;" ::: "memory")
#define CP_WAIT0()  asm volatile("cp.async.wait_group 0;" ::: "memory")

// ==================== device scratch (all 16B-aligned) ====================
// NOTE: all mutable cross-call state is re-zeroed by k_losses at the END of
// every call; device globals are zero-initialized at load, so every
// invocation (correctness run, capture, every replay) starts identically.
__device__ __align__(16) int   g_sel[NT * 2];
__device__ __align__(16) float g_wt[NT * 2];
__device__ __align__(16) int   g_counts[NE];
__device__ __align__(16) int   g_offsets[NE];
__device__ __align__(16) float g_probsum[NE];
__device__ float g_zsum;
__device__ __align__(16) int   g_pair_tok[NPAIRS];
__device__ __align__(16) float g_pair_w[NPAIRS];

__device__ __align__(16) __half g_x_h[NT * NH];
__device__ __align__(16) __half g_wg_h[NE * NI * NH];
__device__ __align__(16) __half g_wu_h[NE * NI * NH];
__device__ __align__(16) __half g_wd_h[NE * NH * NI];
__device__ __align__(16) __half g_h[(size_t)NPAIRS * NI];

// ==================== fused router + fp32->fp16 conversion ================
// Blocks [0, RB) run the router (one warp per token); blocks [RB, ...) run
// the conversion + out-zeroing. Disjoint state -> safe in one kernel.
#define W4 (NE * NI * NH / 4)
#define X4 (NT * NH / 4)
#define O4 (NT * NH / 4)
#define RB (NT / 8)              // 1024 router blocks
#define TOT4 (3L * W4 + X4 + O4) // conversion work items
__global__ void k_front(const float* __restrict__ wg, const float* __restrict__ wu,
                        const float* __restrict__ wd, const float* __restrict__ x,
                        const float* __restrict__ gw, float* __restrict__ out) {
    __shared__ float sgw[NE * NH];
    __shared__ float sprob[NE];
    __shared__ float sz;
    int tid = threadIdx.x;

    if (blockIdx.x >= RB) {
        // ---------------- conversion part ----------------
        long i = (long)(blockIdx.x - RB) * blockDim.x + tid;
        const float* src;
        __half* dst;
        long j;
        if (i < W4)            { src = wg; dst = g_wg_h; j = i; }
        else if (i < 2L * W4)  { src = wu; dst = g_wu_h; j = i - W4; }
        else if (i < 3L * W4)  { src = wd; dst = g_wd_h; j = i - 2L * W4; }
        else if (i < 3L * W4 + X4) { src = x; dst = g_x_h; j = i - 3L * W4; }
        else if (i < TOT4) {
            j = i - (3L * W4 + X4);
            ((float4*)out)[j] = make_float4(0.f, 0.f, 0.f, 0.f);
            return;
        }
        else return;
        float4 v = ((const float4*)src)[j];
        union { __half h[4]; uint2 u; } r;
        r.h[0] = __float2half_rn(v.x);
        r.h[1] = __float2half_rn(v.y);
        r.h[2] = __float2half_rn(v.z);
        r.h[3] = __float2half_rn(v.w);
        ((uint2*)dst)[j] = r.u;
        return;
    }

    // ---------------- router part ----------------
    for (int i = tid; i < NE * NH; i += 256) sgw[i] = gw[i];
    if (tid < NE) sprob[tid] = 0.f;
    if (tid == 0) sz = 0.f;
    __syncthreads();

    int warp = tid >> 5, lane = tid & 31;
    int t = blockIdx.x * 8 + warp;

    float acc[NE];
#pragma unroll
    for (int e = 0; e < NE; e++) acc[e] = 0.f;
    const float* xr = x + (size_t)t * NH;
    for (int j = lane; j < NH; j += 32) {
        float xv = xr[j];
#pragma unroll
        for (int e = 0; e < NE; e++) acc[e] += xv * sgw[e * NH + j];
    }
#pragma unroll
    for (int e = 0; e < NE; e++)
#pragma unroll
        for (int off = 16; off > 0; off >>= 1)
            acc[e] += __shfl_xor_sync(0xffffffffu, acc[e], off);

    if (lane == 0) {
        float m = acc[0];
#pragma unroll
        for (int e = 1; e < NE; e++) m = fmaxf(m, acc[e]);
        float p[NE]; float s = 0.f;
#pragma unroll
        for (int e = 0; e < NE; e++) { p[e] = expf(acc[e] - m); s += p[e]; }
        float inv = 1.f / s;
#pragma unroll
        for (int e = 0; e < NE; e++) p[e] *= inv;

        int i0 = 0; float m0 = p[0];
#pragma unroll
        for (int e = 1; e < NE; e++) if (p[e] > m0) { m0 = p[e]; i0 = e; }
        int i1 = -1; float m1 = -1.f;
#pragma unroll
        for (int e = 0; e < NE; e++) if (e != i0 && p[e] > m1) { m1 = p[e]; i1 = e; }

        float wsum = m0 + m1;
        g_sel[2*t] = i0; g_sel[2*t+1] = i1;
        g_wt[2*t] = m0 / wsum; g_wt[2*t+1] = m1 / wsum;
        atomicAdd(&g_counts[i0], 1);
        atomicAdd(&g_counts[i1], 1);
#pragma unroll
        for (int e = 0; e < NE; e++) atomicAdd(&sprob[e], p[e]);
        float lse = m + logf(s);
        atomicAdd(&sz, lse * lse);
    }
    __syncthreads();
    if (tid < NE) atomicAdd(&g_probsum[tid], sprob[tid]);
    if (tid == 0) atomicAdd(&g_zsum, sz);
}

// ==================== fused offsets + scatter: one block per expert ========
__global__ void k_scatter8() {
    __shared__ int scur;
    __shared__ int soff;
    int e = blockIdx.x;
    int tid = threadIdx.x;
    if (tid == 0) {
        int s = 0;
        for (int q = 0; q < NE; q++) { if (q == e) break; s += g_counts[q]; }
        g_offsets[e] = s;
        soff = s;
        scur = 0;
    }
    __syncthreads();
    int off = soff;
    for (int idx = tid; idx < NPAIRS; idx += blockDim.x) {
        if (g_sel[idx] == e) {
            int pos = atomicAdd(&scur, 1);
            g_pair_tok[off + pos] = idx >> 1;
            g_pair_w[off + pos]   = g_wt[idx];
        }
    }
}

// ==================== HMMA GEMM kernels (KB=64, dynamic smem) ==============
#define KB 64                 // K elements per stage
#define PITCH 144             // bytes per smem row: 128 data + 16 pad
#define STAGE 36864           // ffn1: A 18432 | Bg 9216 | Bu 9216
#define SMEM_DYN (2 * STAGE)  // 73728
#define STAGE2 27648          // ffn2: A 9216 | B 18432
#define SMEM_DYN2 (2 * STAGE2) // 55296
#define TILES_M 64

// ---- pass 1: gate/up GEMM + SwiGLU -> g_h (fp16) ----
// CTA tile M=128 x N=64 (x2 outputs); 128 threads = 4 warps of 64Mx32N(x2)
__global__ void __launch_bounds__(128, 3) k_ffn1() {
    extern __shared__ char smc[];
    __shared__ int s_tok[128];

    int e  = blockIdx.y >> 6;
    int n0 = (blockIdx.y & 63) * 64;
    int row0 = blockIdx.x * 128;
    int cnt = g_counts[e];
    if (row0 >= cnt) return;
    int base = g_offsets[e];
    int tid = threadIdx.x;

    {
        int r = row0 + tid;
        s_tok[tid] = g_pair_tok[base + (r < cnt ? r : cnt - 1)];
    }
    __syncthreads();

    uint32_t sb = smem_u32(smc);

    // cp.async loaders (16B chunks): A 8/thread, Bg 4, Bu 4
    int r0 = tid >> 3, c = tid & 7;          // r0: 0..15, c: 0..7
    const __half* pA[8];
#pragma unroll
    for (int i = 0; i < 8; i++)
        pA[i] = g_x_h + (size_t)s_tok[r0 + 16 * i] * NH + c * 8;
    uint32_t sA0 = sb + r0 * PITCH + c * 16;                 // +i*2304
    const __half* pBg0 = g_wg_h + ((size_t)e * NI + n0 + r0) * NH + c * 8;  // +i*16*NH
    const __half* pBu0 = g_wu_h + ((size_t)e * NI + n0 + r0) * NH + c * 8;
    uint32_t sBg0 = sb + 18432 + r0 * PITCH + c * 16;
    uint32_t sBu0 = sb + 27648 + r0 * PITCH + c * 16;

    int lane = tid & 31, w = tid >> 5;
    int wm = w & 1, wn = w >> 1;          // wm: 64-row half, wn: 32-col half
    int r4 = lane >> 2, c2 = lane & 3;

    float ag[4][4][4], au[4][4][4];
#pragma unroll
    for (int i = 0; i < 4; i++)
#pragma unroll
        for (int j = 0; j < 4; j++)
#pragma unroll
            for (int q = 0; q < 4; q++) { ag[i][j][q] = 0.f; au[i][j][q] = 0.f; }

    // prologue: stage 0
#pragma unroll
    for (int i = 0; i < 8; i++) CP16(sA0 + i * 2304, pA[i]);
#pragma unroll
    for (int i = 0; i < 4; i++) {
        CP16(sBg0 + i * 2304, pBg0 + i * 16 * NH);
        CP16(sBu0 + i * 2304, pBu0 + i * 16 * NH);
    }
    CP_COMMIT();

    const int KT = NH / KB;   // 16
    for (int kt = 0; kt < KT; kt++) {
        CP_WAIT0();
        __syncthreads();
        if (kt + 1 < KT) {
            int ko = (kt + 1) * KB;
            uint32_t off = ((kt + 1) & 1) * STAGE;
#pragma unroll
            for (int i = 0; i < 8; i++) CP16(sA0 + off + i * 2304, pA[i] + ko);
#pragma unroll
            for (int i = 0; i < 4; i++) {
                CP16(sBg0 + off + i * 2304, pBg0 + ko + i * 16 * NH);
                CP16(sBu0 + off + i * 2304, pBu0 + ko + i * 16 * NH);
            }
            CP_COMMIT();
        }
        const char* stg = smc + (kt & 1) * STAGE;
#pragma unroll
        for (int kk = 0; kk < 4; kk++) {
            uint32_t af[4][4];
#pragma unroll
            for (int i = 0; i < 4; i++) {
                const char* ab = stg + (wm * 64 + i * 16 + r4) * PITCH + kk * 32 + c2 * 4;
                af[i][0] = *(const uint32_t*)(ab);
                af[i][1] = *(const uint32_t*)(ab + 8 * PITCH);
                af[i][2] = *(const uint32_t*)(ab + 16);
                af[i][3] = *(const uint32_t*)(ab + 8 * PITCH + 16);
            }
#pragma unroll
            for (int j = 0; j < 4; j++) {
                int n = wn * 32 + j * 8 + r4;
                const char* bb = stg + 18432 + n * PITCH + kk * 32 + c2 * 4;
                uint32_t bg[2], bu[2];
                bg[0] = *(const uint32_t*)(bb);
                bg[1] = *(const uint32_t*)(bb + 16);
                bu[0] = *(const uint32_t*)(bb + 9216);
                bu[1] = *(const uint32_t*)(bb + 9216 + 16);
#pragma unroll
                for (int i = 0; i < 4; i++) {
                    mma16816(ag[i][j], af[i], bg);
                    mma16816(au[i][j], af[i], bu);
                }
            }
        }
    }

    // epilogue: h = silu(g)*u -> fp16
#pragma unroll
    for (int i = 0; i < 4; i++)
#pragma unroll
        for (int rr = 0; rr < 2; rr++) {
            int rl = wm * 64 + i * 16 + r4 + rr * 8;
            int r = row0 + rl;
            if (r < cnt) {
                __half* hrow = g_h + (size_t)(base + r) * NI;
#pragma unroll
                for (int j = 0; j < 4; j++) {
                    int col = n0 + wn * 32 + j * 8 + c2 * 2;
                    float g0 = ag[i][j][rr * 2], g1 = ag[i][j][rr * 2 + 1];
                    float u0 = au[i][j][rr * 2], u1 = au[i][j][rr * 2 + 1];
                    float h0 = g0 / (1.f + expf(-g0)) * u0;
                    float h1 = g1 / (1.f + expf(-g1)) * u1;
                    *(__half2*)(hrow + col) = __floats2half2_rn(h0, h1);
                }
            }
        }
}

// ---- pass 2: out[tok] += w * (h @ Wd^T) ----
// CTA tile M=64 x N=128; 128 threads = 4 warps of 32Mx64N; occupancy 4
__global__ void __launch_bounds__(128, 4) k_ffn2(float* __restrict__ out) {
    extern __shared__ char smc[];
    __shared__ int   s_tok[64];
    __shared__ float s_w[64];

    int e  = blockIdx.y >> 3;
    int n0 = (blockIdx.y & 7) * 128;
    int row0 = blockIdx.x * 64;
    int cnt = g_counts[e];
    if (row0 >= cnt) return;
    int base = g_offsets[e];
    int tid = threadIdx.x;

    if (tid < 64) {
        int r = row0 + tid;
        s_tok[tid] = (r < cnt) ? g_pair_tok[base + r] : 0;
        s_w[tid]   = (r < cnt) ? g_pair_w[base + r] : 0.f;
    }
    __syncthreads();

    uint32_t sb = smem_u32(smc);

    // cp.async loaders: A 4/thread (64 rows, clamped gather), B 8/thread (128 rows)
    int r0 = tid >> 3, c = tid & 7;          // r0: 0..15
    const __half* pA[4];
#pragma unroll
    for (int i = 0; i < 4; i++) {
        int rc = row0 + r0 + 16 * i; if (rc >= cnt) rc = cnt - 1;
        pA[i] = g_h + (size_t)(base + rc) * NI + c * 8;
    }
    uint32_t sA0 = sb + r0 * PITCH + c * 16;                      // +i*2304
    const __half* pB0 = g_wd_h + ((size_t)e * NH + n0 + r0) * NI + c * 8;   // +i*16*NI
    uint32_t sB0 = sb + 9216 + r0 * PITCH + c * 16;               // +i*2304

    int lane = tid & 31, w = tid >> 5;
    int wm = w & 1, wn = w >> 1;          // wm: 32-row half, wn: 64-col half
    int r4 = lane >> 2, c2 = lane & 3;

    float acc[2][8][4];
#pragma unroll
    for (int i = 0; i < 2; i++)
#pragma unroll
        for (int j = 0; j < 8; j++)
#pragma unroll
            for (int q = 0; q < 4; q++) acc[i][j][q] = 0.f;

#pragma unroll
    for (int i = 0; i < 4; i++) CP16(sA0 + i * 2304, pA[i]);
#pragma unroll
    for (int i = 0; i < 8; i++) CP16(sB0 + i * 2304, pB0 + i * 16 * NI);
    CP_COMMIT();

    const int KT = NI / KB;   // 64
    for (int kt = 0; kt < KT; kt++) {
        CP_WAIT0();
        __syncthreads();
        if (kt + 1 < KT) {
            int ko = (kt + 1) * KB;
            uint32_t off = ((kt + 1) & 1) * STAGE2;
#pragma unroll
            for (int i = 0; i < 4; i++) CP16(sA0 + off + i * 2304, pA[i] + ko);
#pragma unroll
            for (int i = 0; i < 8; i++) CP16(sB0 + off + i * 2304, pB0 + ko + i * 16 * NI);
            CP_COMMIT();
        }
        const char* stg = smc + (kt & 1) * STAGE2;
#pragma unroll
        for (int kk = 0; kk < 4; kk++) {
            uint32_t af[2][4];
#pragma unroll
            for (int i = 0; i < 2; i++) {
                const char* ab = stg + (wm * 32 + i * 16 + r4) * PITCH + kk * 32 + c2 * 4;
                af[i][0] = *(const uint32_t*)(ab);
                af[i][1] = *(const uint32_t*)(ab + 8 * PITCH);
                af[i][2] = *(const uint32_t*)(ab + 16);
                af[i][3] = *(const uint32_t*)(ab + 8 * PITCH + 16);
            }
#pragma unroll
            for (int j = 0; j < 8; j++) {
                int n = wn * 64 + j * 8 + r4;
                const char* bb = stg + 9216 + n * PITCH + kk * 32 + c2 * 4;
                uint32_t b[2];
                b[0] = *(const uint32_t*)(bb);
                b[1] = *(const uint32_t*)(bb + 16);
#pragma unroll
                for (int i = 0; i < 2; i++) mma16816(acc[i][j], af[i], b);
            }
        }
    }

    // epilogue: weighted atomic accumulate into out
#pragma unroll
    for (int i = 0; i < 2; i++)
#pragma unroll
        for (int rr = 0; rr < 2; rr++) {
            int rl = wm * 32 + i * 16 + r4 + rr * 8;
            if (row0 + rl < cnt) {
                int tok = s_tok[rl];
                float wt = s_w[rl];
                float* orow = out + (size_t)tok * NH + n0;
#pragma unroll
                for (int j = 0; j < 8; j++) {
                    int col = wn * 64 + j * 8 + c2 * 2;
                    atomicAdd(&orow[col],     wt * acc[i][j][rr * 2]);
                    atomicAdd(&orow[col + 1], wt * acc[i][j][rr * 2 + 1]);
                }
            }
        }
}

// ==================== losses + end-of-call state reset =====================
__global__ void k_losses(float* __restrict__ out, int out_size) {
    if (threadIdx.x == 0 && blockIdx.x == 0) {
        float lb = 0.f;
        for (int e = 0; e < NE; e++)
            lb += ((float)g_counts[e] / (float)NT) * (g_probsum[e] / (float)NT);
        lb *= (float)NE * 0.01f;
        float z = g_zsum / (float)NT * 0.001f;
        if (out_size > NT * NH)     out[NT * NH]     = lb;
        if (out_size > NT * NH + 1) out[NT * NH + 1] = z;
        // reset accumulators for the next call (globals are zero-init at load,
        // so every call sees identical zeroed state at entry)
        for (int e = 0; e < NE; e++) { g_counts[e] = 0; g_probsum[e] = 0.f; }
        g_zsum = 0.f;
    }
}

// ==================== launch ====================
extern "C" void kernel_launch(void* const* d_in, const int* in_sizes, int n_in,
                              void* d_out, int out_size) {
    const float* x  = (const float*)d_in[0];
    const float* gw = (const float*)d_in[1];
    const float* wg = (const float*)d_in[2];
    const float* wu = (const float*)d_in[3];
    const float* wd = (const float*)d_in[4];
    float* out = (float*)d_out;

    cudaFuncSetAttribute(k_ffn1, cudaFuncAttributeMaxDynamicSharedMemorySize, SMEM_DYN);
    cudaFuncSetAttribute(k_ffn2, cudaFuncAttributeMaxDynamicSharedMemorySize, SMEM_DYN2);

    // launch 1: fused router + conversion + out zeroing
    int conv_blocks = (int)((TOT4 + 255) / 256);
    k_front<<<RB + conv_blocks, 256>>>(wg, wu, wd, x, gw, out);

    // launch 2: offsets + scatter
    k_scatter8<<<NE, 256>>>();

    // launch 3: pass-1 GEMM
    dim3 g1(TILES_M, NE * 64);
    k_ffn1<<<g1, 128, SMEM_DYN>>>();

    // launch 4: pass-2 GEMM  (ncu capture slot -> first ffn2 profile)
    dim3 g2(TILES_M * 2, NE * 8);
    k_ffn2<<<g2, 128, SMEM_DYN2>>>(out);

    // launch 5: losses + state reset
    k_losses<<<1, 32>>>(out, out_size);
}

// round 16
// speedup vs baseline: 1.0221x; 1.0221x over previous
#include <cuda_runtime.h>
#include <cuda_fp16.h>
#include <cstdint>
#include <math.h>

// Problem constants
#define NT 8192          // tokens = 4*2048
#define NH 1024          // hidden
#define NE 8             // experts
#define NI 4096          // intermediate
#define NPAIRS (2*NT)    // top-2 pairs

// ==================== PTX helpers ====================
__device__ __forceinline__ void mma16816(float* d, const uint32_t* a, const uint32_t* b) {
    asm volatile("mma.sync.aligned.m16n8k16.row.col.f32.f16.f16.f32 "
        "{%0,%1,%2,%3}, {%4,%5,%6,%7}, {%8,%9}, {%0,%1,%2,%3};"
        : "+f"(d[0]), "+f"(d[1]), "+f"(d[2]), "+f"(d[3])
        : "r"(a[0]), "r"(a[1]), "r"(a[2]), "r"(a[3]), "r"(b[0]), "r"(b[1]));
}
__device__ __forceinline__ uint32_t smem_u32(const void* p) {
    uint32_t a;
    asm("{ .reg .u64 t; cvta.to.shared.u64 t, %1; cvt.u32.u64 %0, t; }" : "=r"(a) : "l"(p));
    return a;
}
#define CP16(sm_addr, gptr) \
    asm volatile("cp.async.ca.shared.global [%0], [%1], 16;" \
                 :: "r"(sm_addr), "l"(gptr) : "memory")
#define CP_COMMIT() asm volatile("cp.async.commit_group;" ::: "memory")
#define CP_WAIT0()  asm volatile("cp.async.wait_group 0;" ::: "memory")

// ==================== device scratch (all 16B-aligned) ====================
// All mutable cross-call accumulators are re-zeroed by k_losses at the END of
// every call; device globals are zero-initialized at load, so every invocation
// (correctness run, capture, every replay) starts from identical state.
__device__ __align__(16) int   g_sel[NT * 2];
__device__ __align__(16) float g_wt[NT * 2];
__device__ __align__(16) int   g_counts[NE];
__device__ __align__(16) int   g_offsets[NE];
__device__ __align__(16) float g_probsum[NE];
__device__ float g_zsum;
__device__ __align__(16) int   g_pair_tok[NPAIRS];
__device__ __align__(16) float g_pair_w[NPAIRS];

__device__ __align__(16) __half g_x_h[NT * NH];
__device__ __align__(16) __half g_wg_h[NE * NI * NH];
__device__ __align__(16) __half g_wu_h[NE * NI * NH];
__device__ __align__(16) __half g_wd_h[NE * NH * NI];
__device__ __align__(16) __half g_h[(size_t)NPAIRS * NI];

// ==================== conversion sweep: wg, wu + out zeroing ===============
// (x is converted inside the router; wd inside k_ffn1's grid)
#define W4 (NE * NI * NH / 4)
#define O4 (NT * NH / 4)
__global__ void k_conv(const float* __restrict__ wg, const float* __restrict__ wu,
                       float* __restrict__ out) {
    long i = (long)blockIdx.x * blockDim.x + threadIdx.x;
    const float* src;
    __half* dst;
    long j;
    if (i < W4)           { src = wg; dst = g_wg_h; j = i; }
    else if (i < 2L * W4) { src = wu; dst = g_wu_h; j = i - W4; }
    else if (i < 2L * W4 + O4) {
        j = i - 2L * W4;
        ((float4*)out)[j] = make_float4(0.f, 0.f, 0.f, 0.f);
        return;
    }
    else return;
    float4 v = ((const float4*)src)[j];
    union { __half h[4]; uint2 u; } r;
    r.h[0] = __float2half_rn(v.x);
    r.h[1] = __float2half_rn(v.y);
    r.h[2] = __float2half_rn(v.z);
    r.h[3] = __float2half_rn(v.w);
    ((uint2*)dst)[j] = r.u;
}

// ==================== router (one warp per token) + x->fp16 ================
__global__ void k_router(const float* __restrict__ x, const float* __restrict__ gw) {
    __shared__ float sgw[NE * NH];
    __shared__ float sprob[NE];
    __shared__ float sz;
    int tid = threadIdx.x;
    for (int i = tid; i < NE * NH; i += 256) sgw[i] = gw[i];
    if (tid < NE) sprob[tid] = 0.f;
    if (tid == 0) sz = 0.f;
    __syncthreads();

    int warp = tid >> 5, lane = tid & 31;
    int t = blockIdx.x * 8 + warp;

    float acc[NE];
#pragma unroll
    for (int e = 0; e < NE; e++) acc[e] = 0.f;
    const float* xr = x + (size_t)t * NH;
    __half* xh = g_x_h + (size_t)t * NH;
    for (int j = lane; j < NH; j += 32) {
        float xv = xr[j];
        xh[j] = __float2half_rn(xv);        // inline x conversion (free: x already read)
#pragma unroll
        for (int e = 0; e < NE; e++) acc[e] += xv * sgw[e * NH + j];
    }
#pragma unroll
    for (int e = 0; e < NE; e++)
#pragma unroll
        for (int off = 16; off > 0; off >>= 1)
            acc[e] += __shfl_xor_sync(0xffffffffu, acc[e], off);

    if (lane == 0) {
        float m = acc[0];
#pragma unroll
        for (int e = 1; e < NE; e++) m = fmaxf(m, acc[e]);
        float p[NE]; float s = 0.f;
#pragma unroll
        for (int e = 0; e < NE; e++) { p[e] = expf(acc[e] - m); s += p[e]; }
        float inv = 1.f / s;
#pragma unroll
        for (int e = 0; e < NE; e++) p[e] *= inv;

        int i0 = 0; float m0 = p[0];
#pragma unroll
        for (int e = 1; e < NE; e++) if (p[e] > m0) { m0 = p[e]; i0 = e; }
        int i1 = -1; float m1 = -1.f;
#pragma unroll
        for (int e = 0; e < NE; e++) if (e != i0 && p[e] > m1) { m1 = p[e]; i1 = e; }

        float wsum = m0 + m1;
        g_sel[2*t] = i0; g_sel[2*t+1] = i1;
        g_wt[2*t] = m0 / wsum; g_wt[2*t+1] = m1 / wsum;
        atomicAdd(&g_counts[i0], 1);
        atomicAdd(&g_counts[i1], 1);
#pragma unroll
        for (int e = 0; e < NE; e++) atomicAdd(&sprob[e], p[e]);
        float lse = m + logf(s);
        atomicAdd(&sz, lse * lse);
    }
    __syncthreads();
    if (tid < NE) atomicAdd(&g_probsum[tid], sprob[tid]);
    if (tid == 0) atomicAdd(&g_zsum, sz);
}

// ==================== fused offsets + scatter: one block per expert ========
__global__ void k_scatter8() {
    __shared__ int scur;
    __shared__ int soff;
    int e = blockIdx.x;
    int tid = threadIdx.x;
    if (tid == 0) {
        int s = 0;
        for (int q = 0; q < NE; q++) { if (q == e) break; s += g_counts[q]; }
        g_offsets[e] = s;
        soff = s;
        scur = 0;
    }
    __syncthreads();
    int off = soff;
    for (int idx = tid; idx < NPAIRS; idx += blockDim.x) {
        if (g_sel[idx] == e) {
            int pos = atomicAdd(&scur, 1);
            g_pair_tok[off + pos] = idx >> 1;
            g_pair_w[off + pos]   = g_wt[idx];
        }
    }
}

// ==================== HMMA GEMM kernels (KB=64, dynamic smem) ==============
#define KB 64                 // K elements per stage
#define PITCH 144             // bytes per smem row: 128 data + 16 pad
#define STAGE 36864           // ffn1: A 18432 | Bg 9216 | Bu 9216
#define SMEM_DYN (2 * STAGE)  // 73728
#define STAGE2 27648          // ffn2: A 9216 | B 18432
#define SMEM_DYN2 (2 * STAGE2) // 55296
#define TILES_M 64
#define CONV_SLICES 16        // leading y-slices of k_ffn1 convert wd

// ---- pass 1: gate/up GEMM + SwiGLU -> g_h (fp16); wd conversion co-tenant --
// GEMM role: CTA tile M=128 x N=64 (x2 outputs); 4 warps of 64Mx32N(x2)
__global__ void __launch_bounds__(128, 3) k_ffn1(const float* __restrict__ wd) {
    extern __shared__ char smc[];
    __shared__ int s_tok[128];

    int by = blockIdx.y;
    if (by < CONV_SLICES) {
        // wd fp32->fp16 conversion, overlapped with the GEMM (DRAM is idle)
        const long STRIDE = (long)CONV_SLICES * TILES_M * 128;
        long id = ((long)by * TILES_M + blockIdx.x) * 128 + threadIdx.x;
        for (long i = id; i < W4; i += STRIDE) {
            float4 v = ((const float4*)wd)[i];
            union { __half h[4]; uint2 u; } r;
            r.h[0] = __float2half_rn(v.x);
            r.h[1] = __float2half_rn(v.y);
            r.h[2] = __float2half_rn(v.z);
            r.h[3] = __float2half_rn(v.w);
            ((uint2*)g_wd_h)[i] = r.u;
        }
        return;
    }
    by -= CONV_SLICES;

    int e  = by >> 6;
    int n0 = (by & 63) * 64;
    int row0 = blockIdx.x * 128;
    int cnt = g_counts[e];
    if (row0 >= cnt) return;
    int base = g_offsets[e];
    int tid = threadIdx.x;

    {
        int r = row0 + tid;
        s_tok[tid] = g_pair_tok[base + (r < cnt ? r : cnt - 1)];
    }
    __syncthreads();

    uint32_t sb = smem_u32(smc);

    // cp.async loaders (16B chunks): A 8/thread, Bg 4, Bu 4
    int r0 = tid >> 3, c = tid & 7;          // r0: 0..15, c: 0..7
    const __half* pA[8];
#pragma unroll
    for (int i = 0; i < 8; i++)
        pA[i] = g_x_h + (size_t)s_tok[r0 + 16 * i] * NH + c * 8;
    uint32_t sA0 = sb + r0 * PITCH + c * 16;                 // +i*2304
    const __half* pBg0 = g_wg_h + ((size_t)e * NI + n0 + r0) * NH + c * 8;  // +i*16*NH
    const __half* pBu0 = g_wu_h + ((size_t)e * NI + n0 + r0) * NH + c * 8;
    uint32_t sBg0 = sb + 18432 + r0 * PITCH + c * 16;
    uint32_t sBu0 = sb + 27648 + r0 * PITCH + c * 16;

    int lane = tid & 31, w = tid >> 5;
    int wm = w & 1, wn = w >> 1;          // wm: 64-row half, wn: 32-col half
    int r4 = lane >> 2, c2 = lane & 3;

    float ag[4][4][4], au[4][4][4];
#pragma unroll
    for (int i = 0; i < 4; i++)
#pragma unroll
        for (int j = 0; j < 4; j++)
#pragma unroll
            for (int q = 0; q < 4; q++) { ag[i][j][q] = 0.f; au[i][j][q] = 0.f; }

    // prologue: stage 0
#pragma unroll
    for (int i = 0; i < 8; i++) CP16(sA0 + i * 2304, pA[i]);
#pragma unroll
    for (int i = 0; i < 4; i++) {
        CP16(sBg0 + i * 2304, pBg0 + i * 16 * NH);
        CP16(sBu0 + i * 2304, pBu0 + i * 16 * NH);
    }
    CP_COMMIT();

    const int KT = NH / KB;   // 16
    for (int kt = 0; kt < KT; kt++) {
        CP_WAIT0();
        __syncthreads();
        if (kt + 1 < KT) {
            int ko = (kt + 1) * KB;
            uint32_t off = ((kt + 1) & 1) * STAGE;
#pragma unroll
            for (int i = 0; i < 8; i++) CP16(sA0 + off + i * 2304, pA[i] + ko);
#pragma unroll
            for (int i = 0; i < 4; i++) {
                CP16(sBg0 + off + i * 2304, pBg0 + ko + i * 16 * NH);
                CP16(sBu0 + off + i * 2304, pBu0 + ko + i * 16 * NH);
            }
            CP_COMMIT();
        }
        const char* stg = smc + (kt & 1) * STAGE;
#pragma unroll
        for (int kk = 0; kk < 4; kk++) {
            uint32_t af[4][4];
#pragma unroll
            for (int i = 0; i < 4; i++) {
                const char* ab = stg + (wm * 64 + i * 16 + r4) * PITCH + kk * 32 + c2 * 4;
                af[i][0] = *(const uint32_t*)(ab);
                af[i][1] = *(const uint32_t*)(ab + 8 * PITCH);
                af[i][2] = *(const uint32_t*)(ab + 16);
                af[i][3] = *(const uint32_t*)(ab + 8 * PITCH + 16);
            }
#pragma unroll
            for (int j = 0; j < 4; j++) {
                int n = wn * 32 + j * 8 + r4;
                const char* bb = stg + 18432 + n * PITCH + kk * 32 + c2 * 4;
                uint32_t bg[2], bu[2];
                bg[0] = *(const uint32_t*)(bb);
                bg[1] = *(const uint32_t*)(bb + 16);
                bu[0] = *(const uint32_t*)(bb + 9216);
                bu[1] = *(const uint32_t*)(bb + 9216 + 16);
#pragma unroll
                for (int i = 0; i < 4; i++) {
                    mma16816(ag[i][j], af[i], bg);
                    mma16816(au[i][j], af[i], bu);
                }
            }
        }
    }

    // epilogue: h = silu(g)*u -> fp16
#pragma unroll
    for (int i = 0; i < 4; i++)
#pragma unroll
        for (int rr = 0; rr < 2; rr++) {
            int rl = wm * 64 + i * 16 + r4 + rr * 8;
            int r = row0 + rl;
            if (r < cnt) {
                __half* hrow = g_h + (size_t)(base + r) * NI;
#pragma unroll
                for (int j = 0; j < 4; j++) {
                    int col = n0 + wn * 32 + j * 8 + c2 * 2;
                    float g0 = ag[i][j][rr * 2], g1 = ag[i][j][rr * 2 + 1];
                    float u0 = au[i][j][rr * 2], u1 = au[i][j][rr * 2 + 1];
                    float h0 = g0 / (1.f + expf(-g0)) * u0;
                    float h1 = g1 / (1.f + expf(-g1)) * u1;
                    *(__half2*)(hrow + col) = __floats2half2_rn(h0, h1);
                }
            }
        }
}

// ---- pass 2: out[tok] += w * (h @ Wd^T) ----
// CTA tile M=64 x N=128; 128 threads = 4 warps of 32Mx64N; occupancy 4
__global__ void __launch_bounds__(128, 4) k_ffn2(float* __restrict__ out) {
    extern __shared__ char smc[];
    __shared__ int   s_tok[64];
    __shared__ float s_w[64];

    int e  = blockIdx.y >> 3;
    int n0 = (blockIdx.y & 7) * 128;
    int row0 = blockIdx.x * 64;
    int cnt = g_counts[e];
    if (row0 >= cnt) return;
    int base = g_offsets[e];
    int tid = threadIdx.x;

    if (tid < 64) {
        int r = row0 + tid;
        s_tok[tid] = (r < cnt) ? g_pair_tok[base + r] : 0;
        s_w[tid]   = (r < cnt) ? g_pair_w[base + r] : 0.f;
    }
    __syncthreads();

    uint32_t sb = smem_u32(smc);

    // cp.async loaders: A 4/thread (64 rows, clamped gather), B 8/thread (128 rows)
    int r0 = tid >> 3, c = tid & 7;          // r0: 0..15
    const __half* pA[4];
#pragma unroll
    for (int i = 0; i < 4; i++) {
        int rc = row0 + r0 + 16 * i; if (rc >= cnt) rc = cnt - 1;
        pA[i] = g_h + (size_t)(base + rc) * NI + c * 8;
    }
    uint32_t sA0 = sb + r0 * PITCH + c * 16;                      // +i*2304
    const __half* pB0 = g_wd_h + ((size_t)e * NH + n0 + r0) * NI + c * 8;   // +i*16*NI
    uint32_t sB0 = sb + 9216 + r0 * PITCH + c * 16;               // +i*2304

    int lane = tid & 31, w = tid >> 5;
    int wm = w & 1, wn = w >> 1;          // wm: 32-row half, wn: 64-col half
    int r4 = lane >> 2, c2 = lane & 3;

    float acc[2][8][4];
#pragma unroll
    for (int i = 0; i < 2; i++)
#pragma unroll
        for (int j = 0; j < 8; j++)
#pragma unroll
            for (int q = 0; q < 4; q++) acc[i][j][q] = 0.f;

#pragma unroll
    for (int i = 0; i < 4; i++) CP16(sA0 + i * 2304, pA[i]);
#pragma unroll
    for (int i = 0; i < 8; i++) CP16(sB0 + i * 2304, pB0 + i * 16 * NI);
    CP_COMMIT();

    const int KT = NI / KB;   // 64
    for (int kt = 0; kt < KT; kt++) {
        CP_WAIT0();
        __syncthreads();
        if (kt + 1 < KT) {
            int ko = (kt + 1) * KB;
            uint32_t off = ((kt + 1) & 1) * STAGE2;
#pragma unroll
            for (int i = 0; i < 4; i++) CP16(sA0 + off + i * 2304, pA[i] + ko);
#pragma unroll
            for (int i = 0; i < 8; i++) CP16(sB0 + off + i * 2304, pB0 + ko + i * 16 * NI);
            CP_COMMIT();
        }
        const char* stg = smc + (kt & 1) * STAGE2;
#pragma unroll
        for (int kk = 0; kk < 4; kk++) {
            uint32_t af[2][4];
#pragma unroll
            for (int i = 0; i < 2; i++) {
                const char* ab = stg + (wm * 32 + i * 16 + r4) * PITCH + kk * 32 + c2 * 4;
                af[i][0] = *(const uint32_t*)(ab);
                af[i][1] = *(const uint32_t*)(ab + 8 * PITCH);
                af[i][2] = *(const uint32_t*)(ab + 16);
                af[i][3] = *(const uint32_t*)(ab + 8 * PITCH + 16);
            }
#pragma unroll
            for (int j = 0; j < 8; j++) {
                int n = wn * 64 + j * 8 + r4;
                const char* bb = stg + 9216 + n * PITCH + kk * 32 + c2 * 4;
                uint32_t b[2];
                b[0] = *(const uint32_t*)(bb);
                b[1] = *(const uint32_t*)(bb + 16);
#pragma unroll
                for (int i = 0; i < 2; i++) mma16816(acc[i][j], af[i], b);
            }
        }
    }

    // epilogue: weighted atomic accumulate into out
#pragma unroll
    for (int i = 0; i < 2; i++)
#pragma unroll
        for (int rr = 0; rr < 2; rr++) {
            int rl = wm * 32 + i * 16 + r4 + rr * 8;
            if (row0 + rl < cnt) {
                int tok = s_tok[rl];
                float wt = s_w[rl];
                float* orow = out + (size_t)tok * NH + n0;
#pragma unroll
                for (int j = 0; j < 8; j++) {
                    int col = wn * 64 + j * 8 + c2 * 2;
                    atomicAdd(&orow[col],     wt * acc[i][j][rr * 2]);
                    atomicAdd(&orow[col + 1], wt * acc[i][j][rr * 2 + 1]);
                }
            }
        }
}

// ==================== losses + end-of-call state reset =====================
__global__ void k_losses(float* __restrict__ out, int out_size) {
    if (threadIdx.x == 0 && blockIdx.x == 0) {
        float lb = 0.f;
        for (int e = 0; e < NE; e++)
            lb += ((float)g_counts[e] / (float)NT) * (g_probsum[e] / (float)NT);
        lb *= (float)NE * 0.01f;
        float z = g_zsum / (float)NT * 0.001f;
        if (out_size > NT * NH)     out[NT * NH]     = lb;
        if (out_size > NT * NH + 1) out[NT * NH + 1] = z;
        // reset accumulators for the next call (globals are zero-init at load,
        // so every call sees identical zeroed state at entry)
        for (int e = 0; e < NE; e++) { g_counts[e] = 0; g_probsum[e] = 0.f; }
        g_zsum = 0.f;
    }
}

// ==================== launch ====================
extern "C" void kernel_launch(void* const* d_in, const int* in_sizes, int n_in,
                              void* d_out, int out_size) {
    const float* x  = (const float*)d_in[0];
    const float* gw = (const float*)d_in[1];
    const float* wg = (const float*)d_in[2];
    const float* wu = (const float*)d_in[3];
    const float* wd = (const float*)d_in[4];
    float* out = (float*)d_out;

    cudaFuncSetAttribute(k_ffn1, cudaFuncAttributeMaxDynamicSharedMemorySize, SMEM_DYN);
    cudaFuncSetAttribute(k_ffn2, cudaFuncAttributeMaxDynamicSharedMemorySize, SMEM_DYN2);

    // launch 1: wg+wu conversion + out zeroing (wd rides inside ffn1; x inside router)
    long conv_items = 2L * W4 + O4;
    k_conv<<<(int)((conv_items + 255) / 256), 256>>>(wg, wu, out);

    // launch 2: router (+ inline x conversion)
    k_router<<<NT / 8, 256>>>(x, gw);

    // launch 3: offsets + scatter
    k_scatter8<<<NE, 256>>>();

    // launch 4: pass-1 GEMM + overlapped wd conversion
    dim3 g1(TILES_M, NE * 64 + CONV_SLICES);
    k_ffn1<<<g1, 128, SMEM_DYN>>>(wd);

    // launch 5: pass-2 GEMM
    dim3 g2(TILES_M * 2, NE * 8);
    k_ffn2<<<g2, 128, SMEM_DYN2>>>(out);

    // launch 6: losses + state reset
    k_losses<<<1, 32>>>(out, out_size);
}

// round 17
// speedup vs baseline: 1.0510x; 1.0283x over previous
#include <cuda_runtime.h>
#include <cuda_fp16.h>
#include <cstdint>
#include <math.h>

// Problem constants
#define NT 8192          // tokens = 4*2048
#define NH 1024          // hidden
#define NE 8             // experts
#define NI 4096          // intermediate
#define NPAIRS (2*NT)    // top-2 pairs

// ==================== PTX helpers ====================
__device__ __forceinline__ void mma16816(float* d, const uint32_t* a, const uint32_t* b) {
    asm volatile("mma.sync.aligned.m16n8k16.row.col.f32.f16.f16.f32 "
        "{%0,%1,%2,%3}, {%4,%5,%6,%7}, {%8,%9}, {%0,%1,%2,%3};"
        : "+f"(d[0]), "+f"(d[1]), "+f"(d[2]), "+f"(d[3])
        : "r"(a[0]), "r"(a[1]), "r"(a[2]), "r"(a[3]), "r"(b[0]), "r"(b[1]));
}
__device__ __forceinline__ uint32_t smem_u32(const void* p) {
    uint32_t a;
    asm("{ .reg .u64 t; cvta.to.shared.u64 t, %1; cvt.u32.u64 %0, t; }" : "=r"(a) : "l"(p));
    return a;
}
#define CP16(sm_addr, gptr) \
    asm volatile("cp.async.ca.shared.global [%0], [%1], 16;" \
                 :: "r"(sm_addr), "l"(gptr) : "memory")
#define CP_COMMIT() asm volatile("cp.async.commit_group;" ::: "memory")
#define CP_WAIT0()  asm volatile("cp.async.wait_group 0;" ::: "memory")

// ==================== device scratch (all 16B-aligned) ====================
// All mutable cross-call accumulators are re-zeroed by k_losses at the END of
// every call; device globals are zero-initialized at load, so every invocation
// (correctness run, capture, every replay) starts from identical state.
__device__ __align__(16) int   g_cnt[NE];            // per-expert pair count (atomic)
__device__ __align__(16) float g_probsum[NE];
__device__ float g_zsum;
__device__ __align__(16) int   g_pair_tok[NE * NT];  // padded per-expert lists
__device__ __align__(16) float g_pair_w[NE * NT];

__device__ __align__(16) __half g_x_h[NT * NH];
__device__ __align__(16) __half g_wg_h[NE * NI * NH];
__device__ __align__(16) __half g_wu_h[NE * NI * NH];
__device__ __align__(16) __half g_wd_h[NE * NH * NI];
__device__ __align__(16) __half g_h[(size_t)NE * NT * NI];  // padded per-expert h rows

// ==================== conversion sweep: wg, wu + out zeroing ===============
// (x is converted inside the router; wd inside k_ffn1's grid)
#define W4 (NE * NI * NH / 4)
#define O4 (NT * NH / 4)
__global__ void k_conv(const float* __restrict__ wg, const float* __restrict__ wu,
                       float* __restrict__ out) {
    long i = (long)blockIdx.x * blockDim.x + threadIdx.x;
    const float* src;
    __half* dst;
    long j;
    if (i < W4)           { src = wg; dst = g_wg_h; j = i; }
    else if (i < 2L * W4) { src = wu; dst = g_wu_h; j = i - W4; }
    else if (i < 2L * W4 + O4) {
        j = i - 2L * W4;
        ((float4*)out)[j] = make_float4(0.f, 0.f, 0.f, 0.f);
        return;
    }
    else return;
    float4 v = ((const float4*)src)[j];
    union { __half h[4]; uint2 u; } r;
    r.h[0] = __float2half_rn(v.x);
    r.h[1] = __float2half_rn(v.y);
    r.h[2] = __float2half_rn(v.z);
    r.h[3] = __float2half_rn(v.w);
    ((uint2*)dst)[j] = r.u;
}

// ==================== router (one warp per token, 16 tok/block) ============
// Writes compacted per-expert pair lists directly (no scatter pass).
__global__ void k_router(const float* __restrict__ x, const float* __restrict__ gw) {
    __shared__ float sgw[NE * NH];
    __shared__ float sprob[NE];
    __shared__ float sz;
    int tid = threadIdx.x;
    for (int i = tid; i < NE * NH; i += 512) sgw[i] = gw[i];
    if (tid < NE) sprob[tid] = 0.f;
    if (tid == 0) sz = 0.f;
    __syncthreads();

    int warp = tid >> 5, lane = tid & 31;
    int t = blockIdx.x * 16 + warp;

    float acc[NE];
#pragma unroll
    for (int e = 0; e < NE; e++) acc[e] = 0.f;
    const float* xr = x + (size_t)t * NH;
    __half* xh = g_x_h + (size_t)t * NH;
    for (int j = lane; j < NH; j += 32) {
        float xv = xr[j];
        xh[j] = __float2half_rn(xv);        // inline x conversion (x already read)
#pragma unroll
        for (int e = 0; e < NE; e++) acc[e] += xv * sgw[e * NH + j];
    }
#pragma unroll
    for (int e = 0; e < NE; e++)
#pragma unroll
        for (int off = 16; off > 0; off >>= 1)
            acc[e] += __shfl_xor_sync(0xffffffffu, acc[e], off);

    if (lane == 0) {
        float m = acc[0];
#pragma unroll
        for (int e = 1; e < NE; e++) m = fmaxf(m, acc[e]);
        float p[NE]; float s = 0.f;
#pragma unroll
        for (int e = 0; e < NE; e++) { p[e] = expf(acc[e] - m); s += p[e]; }
        float inv = 1.f / s;
#pragma unroll
        for (int e = 0; e < NE; e++) p[e] *= inv;

        int i0 = 0; float m0 = p[0];
#pragma unroll
        for (int e = 1; e < NE; e++) if (p[e] > m0) { m0 = p[e]; i0 = e; }
        int i1 = -1; float m1 = -1.f;
#pragma unroll
        for (int e = 0; e < NE; e++) if (e != i0 && p[e] > m1) { m1 = p[e]; i1 = e; }

        float wsum = m0 + m1;
        int p0 = atomicAdd(&g_cnt[i0], 1);
        g_pair_tok[i0 * NT + p0] = t;
        g_pair_w[i0 * NT + p0]   = m0 / wsum;
        int p1 = atomicAdd(&g_cnt[i1], 1);
        g_pair_tok[i1 * NT + p1] = t;
        g_pair_w[i1 * NT + p1]   = m1 / wsum;
#pragma unroll
        for (int e = 0; e < NE; e++) atomicAdd(&sprob[e], p[e]);
        float lse = m + logf(s);
        atomicAdd(&sz, lse * lse);
    }
    __syncthreads();
    if (tid < NE) atomicAdd(&g_probsum[tid], sprob[tid]);
    if (tid == 0) atomicAdd(&g_zsum, sz);
}

// ==================== HMMA GEMM kernels (KB=64, dynamic smem) ==============
#define KB 64                 // K elements per stage
#define PITCH 144             // bytes per smem row: 128 data + 16 pad
#define STAGE 36864           // ffn1: A 18432 | Bg 9216 | Bu 9216
#define SMEM_DYN (2 * STAGE)  // 73728
#define STAGE2 27648          // ffn2: A 9216 | B 18432
#define SMEM_DYN2 (2 * STAGE2) // 55296
#define TILES_M 64
#define CONV_SLICES 16        // leading y-slices of k_ffn1 convert wd

// ---- pass 1: gate/up GEMM + SwiGLU -> g_h (fp16); wd conversion co-tenant --
// GEMM role: CTA tile M=128 x N=64 (x2 outputs); 4 warps of 64Mx32N(x2)
__global__ void __launch_bounds__(128, 3) k_ffn1(const float* __restrict__ wd) {
    extern __shared__ char smc[];
    __shared__ int s_tok[128];

    int by = blockIdx.y;
    if (by < CONV_SLICES) {
        // wd fp32->fp16 conversion, overlapped with the GEMM (DRAM is idle)
        const long STRIDE = (long)CONV_SLICES * TILES_M * 128;
        long id = ((long)by * TILES_M + blockIdx.x) * 128 + threadIdx.x;
        for (long i = id; i < W4; i += STRIDE) {
            float4 v = ((const float4*)wd)[i];
            union { __half h[4]; uint2 u; } r;
            r.h[0] = __float2half_rn(v.x);
            r.h[1] = __float2half_rn(v.y);
            r.h[2] = __float2half_rn(v.z);
            r.h[3] = __float2half_rn(v.w);
            ((uint2*)g_wd_h)[i] = r.u;
        }
        return;
    }
    by -= CONV_SLICES;

    int e  = by >> 6;
    int n0 = (by & 63) * 64;
    int row0 = blockIdx.x * 128;
    int cnt = g_cnt[e];
    if (row0 >= cnt) return;
    int base = e * NT;
    int tid = threadIdx.x;

    {
        int r = row0 + tid;
        s_tok[tid] = g_pair_tok[base + (r < cnt ? r : cnt - 1)];
    }
    __syncthreads();

    uint32_t sb = smem_u32(smc);

    // cp.async loaders (16B chunks): A 8/thread, Bg 4, Bu 4
    int r0 = tid >> 3, c = tid & 7;          // r0: 0..15, c: 0..7
    const __half* pA[8];
#pragma unroll
    for (int i = 0; i < 8; i++)
        pA[i] = g_x_h + (size_t)s_tok[r0 + 16 * i] * NH + c * 8;
    uint32_t sA0 = sb + r0 * PITCH + c * 16;                 // +i*2304
    const __half* pBg0 = g_wg_h + ((size_t)e * NI + n0 + r0) * NH + c * 8;  // +i*16*NH
    const __half* pBu0 = g_wu_h + ((size_t)e * NI + n0 + r0) * NH + c * 8;
    uint32_t sBg0 = sb + 18432 + r0 * PITCH + c * 16;
    uint32_t sBu0 = sb + 27648 + r0 * PITCH + c * 16;

    int lane = tid & 31, w = tid >> 5;
    int wm = w & 1, wn = w >> 1;          // wm: 64-row half, wn: 32-col half
    int r4 = lane >> 2, c2 = lane & 3;

    float ag[4][4][4], au[4][4][4];
#pragma unroll
    for (int i = 0; i < 4; i++)
#pragma unroll
        for (int j = 0; j < 4; j++)
#pragma unroll
            for (int q = 0; q < 4; q++) { ag[i][j][q] = 0.f; au[i][j][q] = 0.f; }

    // prologue: stage 0
#pragma unroll
    for (int i = 0; i < 8; i++) CP16(sA0 + i * 2304, pA[i]);
#pragma unroll
    for (int i = 0; i < 4; i++) {
        CP16(sBg0 + i * 2304, pBg0 + i * 16 * NH);
        CP16(sBu0 + i * 2304, pBu0 + i * 16 * NH);
    }
    CP_COMMIT();

    const int KT = NH / KB;   // 16
    for (int kt = 0; kt < KT; kt++) {
        CP_WAIT0();
        __syncthreads();
        if (kt + 1 < KT) {
            int ko = (kt + 1) * KB;
            uint32_t off = ((kt + 1) & 1) * STAGE;
#pragma unroll
            for (int i = 0; i < 8; i++) CP16(sA0 + off + i * 2304, pA[i] + ko);
#pragma unroll
            for (int i = 0; i < 4; i++) {
                CP16(sBg0 + off + i * 2304, pBg0 + ko + i * 16 * NH);
                CP16(sBu0 + off + i * 2304, pBu0 + ko + i * 16 * NH);
            }
            CP_COMMIT();
        }
        const char* stg = smc + (kt & 1) * STAGE;
#pragma unroll
        for (int kk = 0; kk < 4; kk++) {
            uint32_t af[4][4];
#pragma unroll
            for (int i = 0; i < 4; i++) {
                const char* ab = stg + (wm * 64 + i * 16 + r4) * PITCH + kk * 32 + c2 * 4;
                af[i][0] = *(const uint32_t*)(ab);
                af[i][1] = *(const uint32_t*)(ab + 8 * PITCH);
                af[i][2] = *(const uint32_t*)(ab + 16);
                af[i][3] = *(const uint32_t*)(ab + 8 * PITCH + 16);
            }
#pragma unroll
            for (int j = 0; j < 4; j++) {
                int n = wn * 32 + j * 8 + r4;
                const char* bb = stg + 18432 + n * PITCH + kk * 32 + c2 * 4;
                uint32_t bg[2], bu[2];
                bg[0] = *(const uint32_t*)(bb);
                bg[1] = *(const uint32_t*)(bb + 16);
                bu[0] = *(const uint32_t*)(bb + 9216);
                bu[1] = *(const uint32_t*)(bb + 9216 + 16);
#pragma unroll
                for (int i = 0; i < 4; i++) {
                    mma16816(ag[i][j], af[i], bg);
                    mma16816(au[i][j], af[i], bu);
                }
            }
        }
    }

    // epilogue: h = silu(g)*u -> fp16 (h row r lives at (e*NT + r) in padded g_h)
#pragma unroll
    for (int i = 0; i < 4; i++)
#pragma unroll
        for (int rr = 0; rr < 2; rr++) {
            int rl = wm * 64 + i * 16 + r4 + rr * 8;
            int r = row0 + rl;
            if (r < cnt) {
                __half* hrow = g_h + (size_t)(base + r) * NI;
#pragma unroll
                for (int j = 0; j < 4; j++) {
                    int col = n0 + wn * 32 + j * 8 + c2 * 2;
                    float g0 = ag[i][j][rr * 2], g1 = ag[i][j][rr * 2 + 1];
                    float u0 = au[i][j][rr * 2], u1 = au[i][j][rr * 2 + 1];
                    float h0 = g0 / (1.f + expf(-g0)) * u0;
                    float h1 = g1 / (1.f + expf(-g1)) * u1;
                    *(__half2*)(hrow + col) = __floats2half2_rn(h0, h1);
                }
            }
        }
}

// ---- pass 2: out[tok] += w * (h @ Wd^T) ----
// CTA tile M=64 x N=128; 128 threads = 4 warps of 32Mx64N; occupancy 4
__global__ void __launch_bounds__(128, 4) k_ffn2(float* __restrict__ out) {
    extern __shared__ char smc[];
    __shared__ int   s_tok[64];
    __shared__ float s_w[64];

    int e  = blockIdx.y >> 3;
    int n0 = (blockIdx.y & 7) * 128;
    int row0 = blockIdx.x * 64;
    int cnt = g_cnt[e];
    if (row0 >= cnt) return;
    int base = e * NT;
    int tid = threadIdx.x;

    if (tid < 64) {
        int r = row0 + tid;
        s_tok[tid] = (r < cnt) ? g_pair_tok[base + r] : 0;
        s_w[tid]   = (r < cnt) ? g_pair_w[base + r] : 0.f;
    }
    __syncthreads();

    uint32_t sb = smem_u32(smc);

    // cp.async loaders: A 4/thread (64 rows, clamped gather), B 8/thread (128 rows)
    int r0 = tid >> 3, c = tid & 7;          // r0: 0..15
    const __half* pA[4];
#pragma unroll
    for (int i = 0; i < 4; i++) {
        int rc = row0 + r0 + 16 * i; if (rc >= cnt) rc = cnt - 1;
        pA[i] = g_h + (size_t)(base + rc) * NI + c * 8;
    }
    uint32_t sA0 = sb + r0 * PITCH + c * 16;                      // +i*2304
    const __half* pB0 = g_wd_h + ((size_t)e * NH + n0 + r0) * NI + c * 8;   // +i*16*NI
    uint32_t sB0 = sb + 9216 + r0 * PITCH + c * 16;               // +i*2304

    int lane = tid & 31, w = tid >> 5;
    int wm = w & 1, wn = w >> 1;          // wm: 32-row half, wn: 64-col half
    int r4 = lane >> 2, c2 = lane & 3;

    float acc[2][8][4];
#pragma unroll
    for (int i = 0; i < 2; i++)
#pragma unroll
        for (int j = 0; j < 8; j++)
#pragma unroll
            for (int q = 0; q < 4; q++) acc[i][j][q] = 0.f;

#pragma unroll
    for (int i = 0; i < 4; i++) CP16(sA0 + i * 2304, pA[i]);
#pragma unroll
    for (int i = 0; i < 8; i++) CP16(sB0 + i * 2304, pB0 + i * 16 * NI);
    CP_COMMIT();

    const int KT = NI / KB;   // 64
    for (int kt = 0; kt < KT; kt++) {
        CP_WAIT0();
        __syncthreads();
        if (kt + 1 < KT) {
            int ko = (kt + 1) * KB;
            uint32_t off = ((kt + 1) & 1) * STAGE2;
#pragma unroll
            for (int i = 0; i < 4; i++) CP16(sA0 + off + i * 2304, pA[i] + ko);
#pragma unroll
            for (int i = 0; i < 8; i++) CP16(sB0 + off + i * 2304, pB0 + ko + i * 16 * NI);
            CP_COMMIT();
        }
        const char* stg = smc + (kt & 1) * STAGE2;
#pragma unroll
        for (int kk = 0; kk < 4; kk++) {
            uint32_t af[2][4];
#pragma unroll
            for (int i = 0; i < 2; i++) {
                const char* ab = stg + (wm * 32 + i * 16 + r4) * PITCH + kk * 32 + c2 * 4;
                af[i][0] = *(const uint32_t*)(ab);
                af[i][1] = *(const uint32_t*)(ab + 8 * PITCH);
                af[i][2] = *(const uint32_t*)(ab + 16);
                af[i][3] = *(const uint32_t*)(ab + 8 * PITCH + 16);
            }
#pragma unroll
            for (int j = 0; j < 8; j++) {
                int n = wn * 64 + j * 8 + r4;
                const char* bb = stg + 9216 + n * PITCH + kk * 32 + c2 * 4;
                uint32_t b[2];
                b[0] = *(const uint32_t*)(bb);
                b[1] = *(const uint32_t*)(bb + 16);
#pragma unroll
                for (int i = 0; i < 2; i++) mma16816(acc[i][j], af[i], b);
            }
        }
    }

    // epilogue: weighted atomic accumulate into out
#pragma unroll
    for (int i = 0; i < 2; i++)
#pragma unroll
        for (int rr = 0; rr < 2; rr++) {
            int rl = wm * 32 + i * 16 + r4 + rr * 8;
            if (row0 + rl < cnt) {
                int tok = s_tok[rl];
                float wt = s_w[rl];
                float* orow = out + (size_t)tok * NH + n0;
#pragma unroll
                for (int j = 0; j < 8; j++) {
                    int col = wn * 64 + j * 8 + c2 * 2;
                    atomicAdd(&orow[col],     wt * acc[i][j][rr * 2]);
                    atomicAdd(&orow[col + 1], wt * acc[i][j][rr * 2 + 1]);
                }
            }
        }
}

// ==================== losses + end-of-call state reset =====================
__global__ void k_losses(float* __restrict__ out, int out_size) {
    if (threadIdx.x == 0 && blockIdx.x == 0) {
        float lb = 0.f;
        for (int e = 0; e < NE; e++)
            lb += ((float)g_cnt[e] / (float)NT) * (g_probsum[e] / (float)NT);
        lb *= (float)NE * 0.01f;
        float z = g_zsum / (float)NT * 0.001f;
        if (out_size > NT * NH)     out[NT * NH]     = lb;
        if (out_size > NT * NH + 1) out[NT * NH + 1] = z;
        // reset accumulators for the next call (globals are zero-init at load,
        // so every call sees identical zeroed state at entry)
        for (int e = 0; e < NE; e++) { g_cnt[e] = 0; g_probsum[e] = 0.f; }
        g_zsum = 0.f;
    }
}

// ==================== launch ====================
extern "C" void kernel_launch(void* const* d_in, const int* in_sizes, int n_in,
                              void* d_out, int out_size) {
    const float* x  = (const float*)d_in[0];
    const float* gw = (const float*)d_in[1];
    const float* wg = (const float*)d_in[2];
    const float* wu = (const float*)d_in[3];
    const float* wd = (const float*)d_in[4];
    float* out = (float*)d_out;

    cudaFuncSetAttribute(k_ffn1, cudaFuncAttributeMaxDynamicSharedMemorySize, SMEM_DYN);
    cudaFuncSetAttribute(k_ffn2, cudaFuncAttributeMaxDynamicSharedMemorySize, SMEM_DYN2);

    // launch 1: wg+wu conversion + out zeroing (wd rides inside ffn1; x inside router)
    long conv_items = 2L * W4 + O4;
    k_conv<<<(int)((conv_items + 255) / 256), 256>>>(wg, wu, out);

    // launch 2: router (+ inline x conversion + direct pair-list scatter)
    k_router<<<NT / 16, 512>>>(x, gw);

    // launch 3: pass-1 GEMM + overlapped wd conversion
    dim3 g1(TILES_M, NE * 64 + CONV_SLICES);
    k_ffn1<<<g1, 128, SMEM_DYN>>>(wd);

    // launch 4: pass-2 GEMM
    dim3 g2(TILES_M * 2, NE * 8);
    k_ffn2<<<g2, 128, SMEM_DYN2>>>(out);

    // launch 5: losses + state reset
    k_losses<<<1, 32>>>(out, out_size);
}